// round 1
// baseline (speedup 1.0000x reference)
#include <cuda_runtime.h>
#include <cstdint>

#define THREADS 256
#define S_LEN   1024
#define D_DIM   64
#define TQ      16
#define WSTRIDE 18   // floats; 72B row -> 8B aligned for LDS.64, conflict-light stores

// smem layout (bytes)
#define SM_QS2   0        // 1024 x u64 duplicated q pairs          (8192 B)
#define SM_WS    8192     // ws[1024][18] floats                    (73728 B)
#define SM_RED   81920    // 8 warps x 16 rows partials             (512 B)
#define SM_MAX   82432    // 16 floats
#define SM_INV   82496    // 16 floats
#define SM_TOTAL 82560

__device__ __forceinline__ unsigned long long pack2(float lo, float hi) {
    unsigned long long r;
    asm("mov.b64 %0, {%1, %2};"
        : "=l"(r) : "r"(__float_as_uint(lo)), "r"(__float_as_uint(hi)));
    return r;
}
__device__ __forceinline__ void unpack2(unsigned long long p, float& lo, float& hi) {
    unsigned int a, b;
    asm("mov.b64 {%0, %1}, %2;" : "=r"(a), "=r"(b) : "l"(p));
    lo = __uint_as_float(a); hi = __uint_as_float(b);
}
// acc = a*b + acc, elementwise on packed f32 pairs (Blackwell FFMA2, PTX-only)
#define FMA2(acc, a, b) \
    asm("fma.rn.f32x2 %0, %1, %2, %0;" : "+l"(acc) : "l"(a), "l"(b))

__global__ void __launch_bounds__(THREADS, 2)
attn_kernel(const float* __restrict__ qg,   const float* __restrict__ kg,
            const float* __restrict__ vg,   const float* __restrict__ prevg,
            const float* __restrict__ maskg,const float* __restrict__ scaleg,
            float* __restrict__ outg, float* __restrict__ woutg,
            float* __restrict__ soutg)
{
    extern __shared__ char smem[];
    unsigned long long* qs2 = (unsigned long long*)(smem + SM_QS2);
    float* ws   = (float*)(smem + SM_WS);
    float* red  = (float*)(smem + SM_RED);
    float* smax = (float*)(smem + SM_MAX);
    float* sinv = (float*)(smem + SM_INV);

    const int tid = threadIdx.x;
    const int bid = blockIdx.x;
    const int bh  = bid >> 6;          // batch*head index, 0..127
    const int q0  = (bid & 63) << 4;   // first q row of this tile

    const float sc = *scaleg;

    // ---- stage q tile, duplicated as (q,q) pairs for FFMA2 a-operand ----
    const float* qbase = qg + ((long)bh * S_LEN + q0) * D_DIM;
    for (int i = tid; i < TQ * D_DIM; i += THREADS) {
        float v = qbase[i];
        qs2[i] = pack2(v, v);
    }
    __syncthreads();

    // ---- QK^T : each thread owns s-columns {tid, tid+256, tid+512, tid+768} ----
    const float* kbh = kg + (long)bh * D_DIM * S_LEN;  // k is [B,H,D,S]
    unsigned long long acc[TQ][2];
    #pragma unroll
    for (int qq = 0; qq < TQ; qq++) { acc[qq][0] = 0ULL; acc[qq][1] = 0ULL; }

    for (int d = 0; d < D_DIM; d++) {
        const float* kd = kbh + d * S_LEN + tid;
        float k0 = kd[0], k1 = kd[256], k2 = kd[512], k3 = kd[768];
        unsigned long long kp0 = pack2(k0, k1);
        unsigned long long kp1 = pack2(k2, k3);
        #pragma unroll
        for (int qq = 0; qq < TQ; qq++) {
            unsigned long long qp = qs2[qq * D_DIM + d];  // broadcast LDS.64
            FMA2(acc[qq][0], qp, kp0);
            FMA2(acc[qq][1], qp, kp1);
        }
    }

    // ---- epilogue: scores = acc*mask*scale + prev ; write scores ----
    float sr[TQ][4];
    const float* prow = prevg + ((long)bh * S_LEN + q0) * S_LEN;
    float*       srow = soutg + ((long)bh * S_LEN + q0) * S_LEN;
    const float* mrow = maskg + (long)q0 * S_LEN;
    #pragma unroll
    for (int qq = 0; qq < TQ; qq++) {
        float a0, a1, a2, a3;
        unpack2(acc[qq][0], a0, a1);
        unpack2(acc[qq][1], a2, a3);
        const long ro = (long)qq * S_LEN;
        float s0 = a0 * mrow[ro + tid      ] * sc + prow[ro + tid      ];
        float s1 = a1 * mrow[ro + tid + 256] * sc + prow[ro + tid + 256];
        float s2 = a2 * mrow[ro + tid + 512] * sc + prow[ro + tid + 512];
        float s3 = a3 * mrow[ro + tid + 768] * sc + prow[ro + tid + 768];
        srow[ro + tid      ] = s0;
        srow[ro + tid + 256] = s1;
        srow[ro + tid + 512] = s2;
        srow[ro + tid + 768] = s3;
        sr[qq][0] = s0; sr[qq][1] = s1; sr[qq][2] = s2; sr[qq][3] = s3;
    }

    // ---- row max (shuffle within warp, smem across warps) ----
    {
        float pm[TQ];
        #pragma unroll
        for (int qq = 0; qq < TQ; qq++)
            pm[qq] = fmaxf(fmaxf(sr[qq][0], sr[qq][1]), fmaxf(sr[qq][2], sr[qq][3]));
        #pragma unroll
        for (int off = 16; off >= 1; off >>= 1) {
            #pragma unroll
            for (int qq = 0; qq < TQ; qq++)
                pm[qq] = fmaxf(pm[qq], __shfl_xor_sync(0xffffffffu, pm[qq], off));
        }
        if ((tid & 31) == 0) {
            int w = tid >> 5;
            #pragma unroll
            for (int qq = 0; qq < TQ; qq++) red[w * TQ + qq] = pm[qq];
        }
        __syncthreads();
        if (tid < TQ) {
            float m = red[tid];
            #pragma unroll
            for (int w = 1; w < 8; w++) m = fmaxf(m, red[w * TQ + tid]);
            smax[tid] = m;
        }
        __syncthreads();
    }

    // ---- exp + row sum ----
    {
        float ps[TQ];
        #pragma unroll
        for (int qq = 0; qq < TQ; qq++) {
            float m  = smax[qq];
            float e0 = __expf(sr[qq][0] - m);
            float e1 = __expf(sr[qq][1] - m);
            float e2 = __expf(sr[qq][2] - m);
            float e3 = __expf(sr[qq][3] - m);
            sr[qq][0] = e0; sr[qq][1] = e1; sr[qq][2] = e2; sr[qq][3] = e3;
            ps[qq] = (e0 + e1) + (e2 + e3);
        }
        #pragma unroll
        for (int off = 16; off >= 1; off >>= 1) {
            #pragma unroll
            for (int qq = 0; qq < TQ; qq++)
                ps[qq] += __shfl_xor_sync(0xffffffffu, ps[qq], off);
        }
        if ((tid & 31) == 0) {
            int w = tid >> 5;
            #pragma unroll
            for (int qq = 0; qq < TQ; qq++) red[w * TQ + qq] = ps[qq];
        }
        __syncthreads();
        if (tid < TQ) {
            float t = 0.f;
            #pragma unroll
            for (int w = 0; w < 8; w++) t += red[w * TQ + tid];
            sinv[tid] = 1.0f / t;
        }
        __syncthreads();
    }

    // ---- write normalized weights; stage unnormalized exp in ws[s][q] ----
    {
        float* wrow = woutg + ((long)bh * S_LEN + q0) * S_LEN;
        #pragma unroll
        for (int qq = 0; qq < TQ; qq++) {
            float inv = sinv[qq];
            #pragma unroll
            for (int j = 0; j < 4; j++) {
                int s = tid + j * 256;
                wrow[(long)qq * S_LEN + s] = sr[qq][j] * inv;
                ws[s * WSTRIDE + qq] = sr[qq][j];   // transposed, q contiguous
            }
        }
    }
    __syncthreads();

    // ---- AV: thread = (d = tid&63, s-quarter = tid>>6), 16 q rows packed in pairs ----
    {
        const int d    = tid & 63;
        const int part = tid >> 6;
        const float* vb = vg + (long)bh * S_LEN * D_DIM + d;
        unsigned long long o2[8];
        #pragma unroll
        for (int i = 0; i < 8; i++) o2[i] = 0ULL;
        const int sbase = part * 256;
        #pragma unroll 4
        for (int si = 0; si < 256; si++) {
            int s = sbase + si;
            float vv = vb[(long)s * D_DIM];
            unsigned long long vp = pack2(vv, vv);
            const unsigned long long* wr =
                (const unsigned long long*)(ws + s * WSTRIDE);
            #pragma unroll
            for (int qp = 0; qp < 8; qp++)
                FMA2(o2[qp], wr[qp], vp);   // (w[2qp],w[2qp+1]) * (v,v)
        }
        __syncthreads();   // all reads of ws done before reuse as scratch

        float* oacc = ws;  // reuse: [part][q][d] -> part*1024 + q*64 + d
        #pragma unroll
        for (int qp = 0; qp < 8; qp++) {
            float f0, f1;
            unpack2(o2[qp], f0, f1);
            oacc[part * 1024 + (2 * qp)     * 64 + d] = f0;
            oacc[part * 1024 + (2 * qp + 1) * 64 + d] = f1;
        }
        __syncthreads();

        float* obase = outg + ((long)bh * S_LEN + q0) * D_DIM;
        for (int i = tid; i < TQ * D_DIM; i += THREADS) {
            int qq = i >> 6;
            float sum = oacc[i] + oacc[1024 + i] + oacc[2048 + i] + oacc[3072 + i];
            obase[i] = sum * sinv[qq];
        }
    }
}

extern "C" void kernel_launch(void* const* d_in, const int* in_sizes, int n_in,
                              void* d_out, int out_size) {
    const float* q     = (const float*)d_in[0];
    const float* k     = (const float*)d_in[1];
    const float* v     = (const float*)d_in[2];
    const float* prev  = (const float*)d_in[3];
    const float* mask  = (const float*)d_in[4];
    const float* scale = (const float*)d_in[5];

    // outputs concatenated in tuple order: output, attn_weights, attn_scores
    float* out  = (float*)d_out;
    float* wout = out  + (long)8 * 16 * 1024 * 64;     // 8388608
    float* sout = wout + (long)8 * 16 * 1024 * 1024;   // +134217728

    cudaFuncSetAttribute(attn_kernel,
                         cudaFuncAttributeMaxDynamicSharedMemorySize, SM_TOTAL);
    attn_kernel<<<8 * 16 * 64, THREADS, SM_TOTAL>>>(
        q, k, v, prev, mask, scale, out, wout, sout);
}

// round 2
// speedup vs baseline: 1.1997x; 1.1997x over previous
#include <cuda_runtime.h>
#include <cstdint>

#define THREADS 256
#define S_LEN   1024
#define D_DIM   64
#define NQP     8      // 8 q-row pairs = 16 q rows per CTA tile

typedef unsigned long long u64;

// smem layout (bytes). "big" region is time-multiplexed:
//   phase 1 (QK):        qs2  = u64[8*64]            (4 KB)
//   phase 2 (stage+AV):  ws2  = u64[1024*9]          (73728 B)
//   phase 3 (AV reduce): partf= float[8*1024]        (32 KB)
#define SM_BIG   0
#define SM_RED   73728     // 8 warps x 16 rows
#define SM_MAX   74240     // 16 floats
#define SM_INV   74304     // 16 floats
#define SM_TOTAL 74368

__device__ __forceinline__ u64 pack2(float lo, float hi) {
    u64 r;
    asm("mov.b64 %0, {%1, %2};"
        : "=l"(r) : "r"(__float_as_uint(lo)), "r"(__float_as_uint(hi)));
    return r;
}
__device__ __forceinline__ void unpack2(u64 p, float& lo, float& hi) {
    unsigned int a, b;
    asm("mov.b64 {%0, %1}, %2;" : "=r"(a), "=r"(b) : "l"(p));
    lo = __uint_as_float(a); hi = __uint_as_float(b);
}
// acc = a*b + acc elementwise on packed f32 pairs (Blackwell FFMA2, PTX-only)
#define FMA2(acc, a, b) \
    asm("fma.rn.f32x2 %0, %1, %2, %0;" : "+l"(acc) : "l"(a), "l"(b))

__global__ void __launch_bounds__(THREADS, 2)
attn_kernel(const float* __restrict__ qg,   const float* __restrict__ kg,
            const float* __restrict__ vg,   const float* __restrict__ prevg,
            const float* __restrict__ maskg,const float* __restrict__ scaleg,
            float* __restrict__ outg, float* __restrict__ woutg,
            float* __restrict__ soutg)
{
    extern __shared__ char smem[];
    u64*   qs2   = (u64*)(smem + SM_BIG);
    u64*   ws2   = (u64*)(smem + SM_BIG);
    float* partf = (float*)(smem + SM_BIG);
    float* red   = (float*)(smem + SM_RED);
    float* smax  = (float*)(smem + SM_MAX);
    float* sinv  = (float*)(smem + SM_INV);

    const int tid = threadIdx.x;
    const int bid = blockIdx.x;
    const int bh  = bid >> 6;          // 0..127
    const int q0  = (bid & 63) << 4;   // first q row of tile
    const int s0  = tid << 2;          // 4 contiguous s columns per thread

    const float sc = *scaleg;

    // ---- stage q as row-pairs: qs2[qp*64+d] = (q[2qp][d], q[2qp+1][d]) ----
    const float* qbase = qg + ((long)bh * S_LEN + q0) * D_DIM;
    for (int i = tid; i < NQP * D_DIM; i += THREADS) {
        int qp = i >> 6, d = i & 63;
        qs2[i] = pack2(qbase[(2 * qp) * D_DIM + d],
                       (qbase + D_DIM)[(2 * qp) * D_DIM + d]);
    }
    __syncthreads();

    // ---- QK^T: acc[qp][si] = (score[2qp][s0+si], score[2qp+1][s0+si]) ----
    const float* kbh = kg + (long)bh * D_DIM * S_LEN;  // k is [B,H,D,S]
    u64 acc[NQP][4];
    #pragma unroll
    for (int qp = 0; qp < NQP; qp++)
        { acc[qp][0]=0; acc[qp][1]=0; acc[qp][2]=0; acc[qp][3]=0; }

    for (int d = 0; d < D_DIM; d += 2) {
        float4 ka = *(const float4*)(kbh + (long)d * S_LEN + s0);
        float4 kb = *(const float4*)(kbh + (long)(d + 1) * S_LEN + s0);
        u64 a0 = pack2(ka.x, ka.x), a1 = pack2(ka.y, ka.y),
            a2 = pack2(ka.z, ka.z), a3 = pack2(ka.w, ka.w);
        u64 b0 = pack2(kb.x, kb.x), b1 = pack2(kb.y, kb.y),
            b2 = pack2(kb.z, kb.z), b3 = pack2(kb.w, kb.w);
        #pragma unroll
        for (int qp = 0; qp < NQP; qp++) {
            ulonglong2 qv = *(const ulonglong2*)(qs2 + qp * 64 + d); // LDS.128 broadcast
            FMA2(acc[qp][0], qv.x, a0);
            FMA2(acc[qp][1], qv.x, a1);
            FMA2(acc[qp][2], qv.x, a2);
            FMA2(acc[qp][3], qv.x, a3);
            FMA2(acc[qp][0], qv.y, b0);
            FMA2(acc[qp][1], qv.y, b1);
            FMA2(acc[qp][2], qv.y, b2);
            FMA2(acc[qp][3], qv.y, b3);
        }
    }

    // ---- epilogue: scores = acc*mask*scale + prev (all float4) ----
    float sr[16][4];
    {
        const long rowbase = (long)bh * S_LEN + q0;
        const float* mb = maskg + (long)q0 * S_LEN + s0;
        const float* pb = prevg + rowbase * S_LEN + s0;
        float*       sb = soutg + rowbase * S_LEN + s0;
        #pragma unroll
        for (int qp = 0; qp < NQP; qp++) {
            float a[2][4];
            unpack2(acc[qp][0], a[0][0], a[1][0]);
            unpack2(acc[qp][1], a[0][1], a[1][1]);
            unpack2(acc[qp][2], a[0][2], a[1][2]);
            unpack2(acc[qp][3], a[0][3], a[1][3]);
            #pragma unroll
            for (int h = 0; h < 2; h++) {
                const int q = 2 * qp + h;
                float4 m = *(const float4*)(mb + (long)q * S_LEN);
                float4 p = *(const float4*)(pb + (long)q * S_LEN);
                float4 s;
                s.x = a[h][0] * m.x * sc + p.x;
                s.y = a[h][1] * m.y * sc + p.y;
                s.z = a[h][2] * m.z * sc + p.z;
                s.w = a[h][3] * m.w * sc + p.w;
                *(float4*)(sb + (long)q * S_LEN) = s;
                sr[q][0] = s.x; sr[q][1] = s.y; sr[q][2] = s.z; sr[q][3] = s.w;
            }
        }
    }

    // ---- row max ----
    {
        float pm[16];
        #pragma unroll
        for (int q = 0; q < 16; q++)
            pm[q] = fmaxf(fmaxf(sr[q][0], sr[q][1]), fmaxf(sr[q][2], sr[q][3]));
        #pragma unroll
        for (int off = 16; off >= 1; off >>= 1) {
            #pragma unroll
            for (int q = 0; q < 16; q++)
                pm[q] = fmaxf(pm[q], __shfl_xor_sync(0xffffffffu, pm[q], off));
        }
        if ((tid & 31) == 0) {
            int w = tid >> 5;
            #pragma unroll
            for (int q = 0; q < 16; q++) red[w * 16 + q] = pm[q];
        }
        __syncthreads();
        if (tid < 16) {
            float m = red[tid];
            #pragma unroll
            for (int w = 1; w < 8; w++) m = fmaxf(m, red[w * 16 + tid]);
            smax[tid] = m;
        }
        __syncthreads();
    }

    // ---- exp + row sum ----
    {
        float ps[16];
        #pragma unroll
        for (int q = 0; q < 16; q++) {
            float m  = smax[q];
            float e0 = __expf(sr[q][0] - m);
            float e1 = __expf(sr[q][1] - m);
            float e2 = __expf(sr[q][2] - m);
            float e3 = __expf(sr[q][3] - m);
            sr[q][0] = e0; sr[q][1] = e1; sr[q][2] = e2; sr[q][3] = e3;
            ps[q] = (e0 + e1) + (e2 + e3);
        }
        #pragma unroll
        for (int off = 16; off >= 1; off >>= 1) {
            #pragma unroll
            for (int q = 0; q < 16; q++)
                ps[q] += __shfl_xor_sync(0xffffffffu, ps[q], off);
        }
        if ((tid & 31) == 0) {
            int w = tid >> 5;
            #pragma unroll
            for (int q = 0; q < 16; q++) red[w * 16 + q] = ps[q];
        }
        __syncthreads();
        if (tid < 16) {
            float t = 0.f;
            #pragma unroll
            for (int w = 0; w < 8; w++) t += red[w * 16 + tid];
            sinv[tid] = 1.0f / t;
        }
        __syncthreads();   // also: all QK reads of qs2 done -> ws2 region free
    }

    // ---- write normalized weights (float4); stage unnormalized pairs ws2[s][qp] ----
    {
        float* wb = woutg + ((long)bh * S_LEN + q0) * S_LEN + s0;
        #pragma unroll
        for (int qp = 0; qp < NQP; qp++) {
            const int qa = 2 * qp, qb2 = 2 * qp + 1;
            const float ia = sinv[qa], ib = sinv[qb2];
            float4 wa = { sr[qa][0]*ia, sr[qa][1]*ia, sr[qa][2]*ia, sr[qa][3]*ia };
            float4 wbv = { sr[qb2][0]*ib, sr[qb2][1]*ib, sr[qb2][2]*ib, sr[qb2][3]*ib };
            *(float4*)(wb + (long)qa  * S_LEN) = wa;
            *(float4*)(wb + (long)qb2 * S_LEN) = wbv;
            #pragma unroll
            for (int si = 0; si < 4; si++)
                ws2[(long)(s0 + si) * 9 + qp] = pack2(sr[qa][si], sr[qb2][si]);
        }
    }
    __syncthreads();

    // ---- AV: warp = s-partition (128 s), lanes = 2 qg x 16 dg ----
    {
        const int sp  = tid >> 5;            // warp id: s in [sp*128, sp*128+128)
        const int dg  = tid & 15;
        const int qg  = (tid >> 4) & 1;
        const int d0  = dg * 4;
        const int qp0 = qg * 4;

        const float* vb = vg + (long)bh * S_LEN * D_DIM + d0;
        u64 o[4][4];
        #pragma unroll
        for (int j = 0; j < 4; j++)
            { o[j][0]=0; o[j][1]=0; o[j][2]=0; o[j][3]=0; }

        const int sbase = sp * 128;
        for (int si = 0; si < 128; si++) {
            const int s = sbase + si;
            float4 vv = *(const float4*)(vb + (long)s * D_DIM);
            u64 v0 = pack2(vv.x, vv.x), v1 = pack2(vv.y, vv.y),
                v2 = pack2(vv.z, vv.z), v3 = pack2(vv.w, vv.w);
            const u64* wr = ws2 + (long)s * 9 + qp0;
            u64 w0 = wr[0], w1 = wr[1], w2 = wr[2], w3 = wr[3];
            FMA2(o[0][0], w0, v0); FMA2(o[0][1], w0, v1);
            FMA2(o[0][2], w0, v2); FMA2(o[0][3], w0, v3);
            FMA2(o[1][0], w1, v0); FMA2(o[1][1], w1, v1);
            FMA2(o[1][2], w1, v2); FMA2(o[1][3], w1, v3);
            FMA2(o[2][0], w2, v0); FMA2(o[2][1], w2, v1);
            FMA2(o[2][2], w2, v2); FMA2(o[2][3], w2, v3);
            FMA2(o[3][0], w3, v0); FMA2(o[3][1], w3, v1);
            FMA2(o[3][2], w3, v2); FMA2(o[3][3], w3, v3);
        }
        __syncthreads();   // all ws2 reads done before partf overwrites region

        // store partials: partf[sp*1024 + q*64 + d]
        #pragma unroll
        for (int j = 0; j < 4; j++) {
            const int q = 2 * (qp0 + j);
            #pragma unroll
            for (int di = 0; di < 4; di++) {
                float f0, f1;
                unpack2(o[j][di], f0, f1);
                partf[sp * 1024 + q       * 64 + d0 + di] = f0;
                partf[sp * 1024 + (q + 1) * 64 + d0 + di] = f1;
            }
        }
        __syncthreads();

        float* ob = outg + ((long)bh * S_LEN + q0) * D_DIM;
        for (int i = tid; i < 16 * D_DIM; i += THREADS) {
            float sum = 0.f;
            #pragma unroll
            for (int p = 0; p < 8; p++) sum += partf[p * 1024 + i];
            ob[i] = sum * sinv[i >> 6];
        }
    }
}

extern "C" void kernel_launch(void* const* d_in, const int* in_sizes, int n_in,
                              void* d_out, int out_size) {
    const float* q     = (const float*)d_in[0];
    const float* k     = (const float*)d_in[1];
    const float* v     = (const float*)d_in[2];
    const float* prev  = (const float*)d_in[3];
    const float* mask  = (const float*)d_in[4];
    const float* scale = (const float*)d_in[5];

    // outputs concatenated in tuple order: output, attn_weights, attn_scores
    float* out  = (float*)d_out;
    float* wout = out  + (long)8 * 16 * 1024 * 64;     // 8388608
    float* sout = wout + (long)8 * 16 * 1024 * 1024;   // +134217728

    cudaFuncSetAttribute(attn_kernel,
                         cudaFuncAttributeMaxDynamicSharedMemorySize, SM_TOTAL);
    attn_kernel<<<8 * 16 * 64, THREADS, SM_TOTAL>>>(
        q, k, v, prev, mask, scale, out, wout, sout);
}

// round 4
// speedup vs baseline: 1.8159x; 1.5136x over previous
#include <cuda_runtime.h>
#include <cstdint>

typedef unsigned int u32;
typedef unsigned long long u64;

#define S_LEN   1024
#define D_DIM   64
#define CHUNK   128
#define NCHUNK  8
#define THREADS 256

// smem (bytes): QH 0..16K, QL 16K..32K, then two k/v hi+lo buffers
#define QH_OFF   0
#define QL_OFF   16384
#define B0_OFF   32768     // bufH = 32768 + buf*32768 ; bufL = bufH + 16384
#define SM_TOTAL 98304

__device__ __forceinline__ u32 smem_u32(const void* p) {
    u32 a;
    asm("{ .reg .u64 t; cvta.to.shared.u64 t, %1; cvt.u32.u64 %0, t; }"
        : "=r"(a) : "l"(p));
    return a;
}
__device__ __forceinline__ u32 swz(u32 b) { return b ^ ((b >> 3) & 0x70); }

// split two floats -> packed bf16x2 hi word + bf16x2 residual word (lo = first arg)
__device__ __forceinline__ void split2(float a, float b, u32& hw, u32& lw) {
    asm("cvt.rn.bf16x2.f32 %0, %1, %2;" : "=r"(hw) : "f"(b), "f"(a));
    float af  = __uint_as_float(hw << 16);
    float bf_ = __uint_as_float(hw & 0xffff0000u);
    asm("cvt.rn.bf16x2.f32 %0, %1, %2;" : "=r"(lw) : "f"(b - bf_), "f"(a - af));
}

#define LDSM4(r0,r1,r2,r3,addr) \
    asm volatile("ldmatrix.sync.aligned.m8n8.x4.shared.b16 {%0,%1,%2,%3}, [%4];" \
        : "=r"(r0),"=r"(r1),"=r"(r2),"=r"(r3) : "r"(addr))
#define LDSM4T(r0,r1,r2,r3,addr) \
    asm volatile("ldmatrix.sync.aligned.m8n8.x4.trans.shared.b16 {%0,%1,%2,%3}, [%4];" \
        : "=r"(r0),"=r"(r1),"=r"(r2),"=r"(r3) : "r"(addr))
#define MMA(c,a0,a1,a2,a3,b0,b1) \
    asm volatile("mma.sync.aligned.m16n8k16.row.col.f32.bf16.bf16.f32 " \
        "{%0,%1,%2,%3},{%4,%5,%6,%7},{%8,%9},{%0,%1,%2,%3};" \
        : "+f"((c)[0]),"+f"((c)[1]),"+f"((c)[2]),"+f"((c)[3]) \
        : "r"(a0),"r"(a1),"r"(a2),"r"(a3),"r"(b0),"r"(b1))

__device__ __forceinline__ void stage_q(char* smem, const float* qb, int tid) {
    for (int it = tid; it < 2048; it += THREADS) {
        int r = it >> 4, d4 = it & 15;
        float4 v = *(const float4*)(qb + r * 64 + d4 * 4);
        u32 h0, l0, h1, l1;
        split2(v.x, v.y, h0, l0);
        split2(v.z, v.w, h1, l1);
        u32 o = swz((u32)(r * 128 + d4 * 8));
        *(u64*)(smem + QH_OFF + o) = ((u64)h1 << 32) | h0;
        *(u64*)(smem + QL_OFF + o) = ((u64)l1 << 32) | l0;
    }
}
// k gmem [d][s] -> smem [s][d] bf16 hi/lo
__device__ __forceinline__ void stage_k(char* smem, const float* kc, int buf, int tid) {
    char* bh = smem + B0_OFF + buf * 32768;
    char* bl = bh + 16384;
    for (int it = tid; it < 1024; it += THREADS) {
        int d2 = it >> 5, s4 = it & 31;
        const float* p0 = kc + (long)(2 * d2) * S_LEN + s4 * 4;
        float4 ka = *(const float4*)p0;
        float4 kb = *(const float4*)(p0 + S_LEN);
        float av[4] = {ka.x, ka.y, ka.z, ka.w};
        float bv[4] = {kb.x, kb.y, kb.z, kb.w};
        #pragma unroll
        for (int j = 0; j < 4; j++) {
            int row = s4 * 4 + j;
            u32 h, l;
            split2(av[j], bv[j], h, l);
            u32 o = swz((u32)(row * 128 + d2 * 4));
            *(u32*)(bh + o) = h;
            *(u32*)(bl + o) = l;
        }
    }
}
// v gmem [s][d] -> smem [s][d] bf16 hi/lo
__device__ __forceinline__ void stage_v(char* smem, const float* vc, int buf, int tid) {
    char* bh = smem + B0_OFF + buf * 32768;
    char* bl = bh + 16384;
    for (int it = tid; it < 2048; it += THREADS) {
        int r = it >> 4, d4 = it & 15;
        float4 v = *(const float4*)(vc + r * 64 + d4 * 4);
        u32 h0, l0, h1, l1;
        split2(v.x, v.y, h0, l0);
        split2(v.z, v.w, h1, l1);
        u32 o = swz((u32)(r * 128 + d4 * 8));
        *(u64*)(bh + o) = ((u64)h1 << 32) | h0;
        *(u64*)(bl + o) = ((u64)l1 << 32) | l0;
    }
}

__global__ void __launch_bounds__(THREADS, 2)
attn_mma(const float* __restrict__ qg,    const float* __restrict__ kg,
         const float* __restrict__ vg,    const float* __restrict__ prevg,
         const float* __restrict__ maskg, const float* __restrict__ scaleg,
         float* __restrict__ outg, float* __restrict__ woutg,
         float* __restrict__ soutg)
{
    extern __shared__ char smem[];
    const u32 sb  = smem_u32(smem);
    const int tid = threadIdx.x, wid = tid >> 5, lid = tid & 31;
    const int bh  = blockIdx.x >> 3;
    const int q0  = (blockIdx.x & 7) << 7;
    const int qw  = wid << 4;                 // warp's first q row in tile

    const float sc = *scaleg;

    stage_q(smem, qg + ((long)bh * S_LEN + q0) * D_DIM, tid);
    stage_k(smem, kg + (long)bh * D_DIM * S_LEN + 0 * CHUNK, 0, tid);
    __syncthreads();

    // persistent A (q) hi fragments: 4 k-steps
    u32 ah[4][4];
    {
        u32 ao = (u32)((qw + (lid & 15)) * 128 + (lid >> 4) * 16);
        #pragma unroll
        for (int ks = 0; ks < 4; ks++) {
            u32 addr = sb + QH_OFF + swz(ao + ks * 32);
            LDSM4(ah[ks][0], ah[ks][1], ah[ks][2], ah[ks][3], addr);
        }
    }

    const int  rl   = lid >> 2;
    const int  cb   = 2 * (lid & 3);
    const long rglo = q0 + qw + rl;           // global q row (lo half)
    const long rghi = rglo + 8;

    float m_lo = -3.4e38f, m_hi = -3.4e38f, s_lo = 0.f, s_hi = 0.f;

    const u32 brow = (u32)((lid & 7) + ((lid >> 4) << 3));
    const u32 bcol = (u32)(((lid >> 3) & 1) << 3);

    // ================= Phase A: QK + scores + online softmax stats =================
    for (int c = 0; c < NCHUNK; c++) {
        if (c < NCHUNK - 1)
            stage_k(smem, kg + (long)bh * D_DIM * S_LEN + (c + 1) * CHUNK,
                    (c + 1) & 1, tid);

        float acc[16][4];
        #pragma unroll
        for (int nt = 0; nt < 16; nt++)
            { acc[nt][0]=0.f; acc[nt][1]=0.f; acc[nt][2]=0.f; acc[nt][3]=0.f; }

        const u32 kh = sb + B0_OFF + (u32)((c & 1) * 32768);
        const u32 kl = kh + 16384;
        const u32 aq = (u32)((qw + (lid & 15)) * 128 + (lid >> 4) * 16);

        #pragma unroll
        for (int ks = 0; ks < 4; ks++) {
            u32 al0, al1, al2, al3;
            LDSM4(al0, al1, al2, al3, sb + QL_OFF + swz(aq + ks * 32));
            #pragma unroll
            for (int np = 0; np < 8; np++) {
                u32 off = swz((u32)((np * 16 + brow) * 128 + (ks * 16 + bcol) * 2));
                u32 h0, h1, h2, h3, l0, l1, l2, l3;
                LDSM4(h0, h1, h2, h3, kh + off);
                LDSM4(l0, l1, l2, l3, kl + off);
                MMA(acc[2*np],   ah[ks][0],ah[ks][1],ah[ks][2],ah[ks][3], h0, h1);
                MMA(acc[2*np+1], ah[ks][0],ah[ks][1],ah[ks][2],ah[ks][3], h2, h3);
                MMA(acc[2*np],   ah[ks][0],ah[ks][1],ah[ks][2],ah[ks][3], l0, l1);
                MMA(acc[2*np+1], ah[ks][0],ah[ks][1],ah[ks][2],ah[ks][3], l2, l3);
                MMA(acc[2*np],   al0,al1,al2,al3, h0, h1);
                MMA(acc[2*np+1], al0,al1,al2,al3, h2, h3);
            }
        }

        // epilogue: s = a*mask*sc + prev ; write scores ; chunk max
        const float* mplo = maskg + rglo * S_LEN + c * CHUNK + cb;
        const float* mphi = maskg + rghi * S_LEN + c * CHUNK + cb;
        const float* pplo = prevg + ((long)bh * S_LEN + rglo) * S_LEN + c * CHUNK + cb;
        const float* pphi = prevg + ((long)bh * S_LEN + rghi) * S_LEN + c * CHUNK + cb;
        float* splo = soutg + ((long)bh * S_LEN + rglo) * S_LEN + c * CHUNK + cb;
        float* sphi = soutg + ((long)bh * S_LEN + rghi) * S_LEN + c * CHUNK + cb;

        float cm_lo = -3.4e38f, cm_hi = -3.4e38f;
        #pragma unroll
        for (int nt = 0; nt < 16; nt++) {
            const int so = nt * 8;
            float2 ml = *(const float2*)(mplo + so);
            float2 mh = *(const float2*)(mphi + so);
            float2 pl = *(const float2*)(pplo + so);
            float2 ph = *(const float2*)(pphi + so);
            acc[nt][0] = acc[nt][0] * ml.x * sc + pl.x;
            acc[nt][1] = acc[nt][1] * ml.y * sc + pl.y;
            acc[nt][2] = acc[nt][2] * mh.x * sc + ph.x;
            acc[nt][3] = acc[nt][3] * mh.y * sc + ph.y;
            float2 olo = {acc[nt][0], acc[nt][1]};
            float2 ohi = {acc[nt][2], acc[nt][3]};
            *(float2*)(splo + so) = olo;
            *(float2*)(sphi + so) = ohi;
            cm_lo = fmaxf(cm_lo, fmaxf(acc[nt][0], acc[nt][1]));
            cm_hi = fmaxf(cm_hi, fmaxf(acc[nt][2], acc[nt][3]));
        }
        cm_lo = fmaxf(cm_lo, __shfl_xor_sync(0xffffffffu, cm_lo, 1));
        cm_lo = fmaxf(cm_lo, __shfl_xor_sync(0xffffffffu, cm_lo, 2));
        cm_hi = fmaxf(cm_hi, __shfl_xor_sync(0xffffffffu, cm_hi, 1));
        cm_hi = fmaxf(cm_hi, __shfl_xor_sync(0xffffffffu, cm_hi, 2));
        float nm_lo = fmaxf(m_lo, cm_lo), nm_hi = fmaxf(m_hi, cm_hi);
        float cs_lo = 0.f, cs_hi = 0.f;
        #pragma unroll
        for (int nt = 0; nt < 16; nt++) {
            cs_lo += __expf(acc[nt][0] - nm_lo) + __expf(acc[nt][1] - nm_lo);
            cs_hi += __expf(acc[nt][2] - nm_hi) + __expf(acc[nt][3] - nm_hi);
        }
        s_lo = s_lo * __expf(m_lo - nm_lo) + cs_lo;  m_lo = nm_lo;
        s_hi = s_hi * __expf(m_hi - nm_hi) + cs_hi;  m_hi = nm_hi;

        __syncthreads();
    }

    // finalize: reduce partial sums across the 4-lane column group
    s_lo += __shfl_xor_sync(0xffffffffu, s_lo, 1);
    s_lo += __shfl_xor_sync(0xffffffffu, s_lo, 2);
    s_hi += __shfl_xor_sync(0xffffffffu, s_hi, 1);
    s_hi += __shfl_xor_sync(0xffffffffu, s_hi, 2);
    const float inv_lo = 1.0f / s_lo, inv_hi = 1.0f / s_hi;

    // ================= Phase B: weights + AV =================
    float out2[8][4];
    #pragma unroll
    for (int nt = 0; nt < 8; nt++)
        { out2[nt][0]=0.f; out2[nt][1]=0.f; out2[nt][2]=0.f; out2[nt][3]=0.f; }

    stage_v(smem, vg + ((long)bh * S_LEN + 0 * CHUNK) * D_DIM, 0, tid);
    __syncthreads();

    const u32 vrow = (u32)((lid & 7) + (((lid >> 3) & 1) << 3));
    const u32 vcol = (u32)((lid >> 4) << 3);

    for (int c = 0; c < NCHUNK; c++) {
        if (c < NCHUNK - 1)
            stage_v(smem, vg + ((long)bh * S_LEN + (c + 1) * CHUNK) * D_DIM,
                    (c + 1) & 1, tid);

        const u32 vh = sb + B0_OFF + (u32)((c & 1) * 32768);
        const u32 vl = vh + 16384;
        const float* slp = soutg + ((long)bh * S_LEN + rglo) * S_LEN + c * CHUNK + cb;
        const float* shp = soutg + ((long)bh * S_LEN + rghi) * S_LEN + c * CHUNK + cb;
        float* wlp = woutg + ((long)bh * S_LEN + rglo) * S_LEN + c * CHUNK + cb;
        float* whp = woutg + ((long)bh * S_LEN + rghi) * S_LEN + c * CHUNK + cb;

        #pragma unroll
        for (int ks = 0; ks < 8; ks++) {
            const int so = ks * 16;
            float2 x0 = *(const float2*)(slp + so);
            float2 x1 = *(const float2*)(slp + so + 8);
            float2 y0 = *(const float2*)(shp + so);
            float2 y1 = *(const float2*)(shp + so + 8);
            float w00 = __expf(x0.x - m_lo) * inv_lo;
            float w01 = __expf(x0.y - m_lo) * inv_lo;
            float w02 = __expf(x1.x - m_lo) * inv_lo;
            float w03 = __expf(x1.y - m_lo) * inv_lo;
            float w10 = __expf(y0.x - m_hi) * inv_hi;
            float w11 = __expf(y0.y - m_hi) * inv_hi;
            float w12 = __expf(y1.x - m_hi) * inv_hi;
            float w13 = __expf(y1.y - m_hi) * inv_hi;
            float2 o;
            o.x = w00; o.y = w01; *(float2*)(wlp + so)     = o;
            o.x = w02; o.y = w03; *(float2*)(wlp + so + 8) = o;
            o.x = w10; o.y = w11; *(float2*)(whp + so)     = o;
            o.x = w12; o.y = w13; *(float2*)(whp + so + 8) = o;

            u32 a0, a1, a2, a3, e0, e1, e2, e3;
            split2(w00, w01, a0, e0);   // row lo, cols cb,cb+1
            split2(w10, w11, a1, e1);   // row hi
            split2(w02, w03, a2, e2);   // row lo, cols +8
            split2(w12, w13, a3, e3);   // row hi, cols +8

            #pragma unroll
            for (int dp = 0; dp < 4; dp++) {
                u32 off = swz((u32)((so + vrow) * 128 + (dp * 16 + vcol) * 2));
                u32 h0, h1, h2, h3, l0, l1, l2, l3;
                LDSM4T(h0, h1, h2, h3, vh + off);
                LDSM4T(l0, l1, l2, l3, vl + off);
                MMA(out2[2*dp],   a0,a1,a2,a3, h0, h1);
                MMA(out2[2*dp+1], a0,a1,a2,a3, h2, h3);
                MMA(out2[2*dp],   a0,a1,a2,a3, l0, l1);
                MMA(out2[2*dp+1], a0,a1,a2,a3, l2, l3);
                MMA(out2[2*dp],   e0,e1,e2,e3, h0, h1);
                MMA(out2[2*dp+1], e0,e1,e2,e3, h2, h3);
            }
        }
        __syncthreads();
    }

    // ---- output (weights were pre-normalized -> out2 is final) ----
    {
        float* olo = outg + ((long)bh * S_LEN + rglo) * D_DIM + cb;
        float* ohi = outg + ((long)bh * S_LEN + rghi) * D_DIM + cb;
        #pragma unroll
        for (int nt = 0; nt < 8; nt++) {
            float2 a = {out2[nt][0], out2[nt][1]};
            float2 b = {out2[nt][2], out2[nt][3]};
            *(float2*)(olo + nt * 8) = a;
            *(float2*)(ohi + nt * 8) = b;
        }
    }
}

extern "C" void kernel_launch(void* const* d_in, const int* in_sizes, int n_in,
                              void* d_out, int out_size) {
    const float* q     = (const float*)d_in[0];
    const float* k     = (const float*)d_in[1];
    const float* v     = (const float*)d_in[2];
    const float* prev  = (const float*)d_in[3];
    const float* mask  = (const float*)d_in[4];
    const float* scale = (const float*)d_in[5];

    float* out  = (float*)d_out;
    float* wout = out  + (long)8 * 16 * 1024 * 64;
    float* sout = wout + (long)8 * 16 * 1024 * 1024;

    cudaFuncSetAttribute(attn_mma,
                         cudaFuncAttributeMaxDynamicSharedMemorySize, SM_TOTAL);
    attn_mma<<<8 * 16 * 8, THREADS, SM_TOTAL>>>(
        q, k, v, prev, mask, scale, out, wout, sout);
}